// round 16
// baseline (speedup 1.0000x reference)
#include <cuda_runtime.h>
#include <cuda_bf16.h>
#include <cuda_fp16.h>
#include <cstdint>

#define SEQ   2048
#define NTOK  8192

// ---------------- scratch (device globals: no runtime allocation) ----------
// fp16 split layout: [row][k/32][32 hi | 32 lo] (128B chunk-rows)
__device__ __half g_xs     [(size_t)NTOK * 2048];   // x split (K=1024)
__device__ __half g_qlat_h [(size_t)NTOK * 128];    // latents split (K=64)
__device__ __half g_kvlat_h[(size_t)NTOK * 128];
__device__ __half g_ysh    [(size_t)NTOK * 2048];   // y split (K=1024)
// plain fp16 weights [n][k] row-major
__device__ __half g_wlat_h [(size_t)128  * 1024];   // [Wq(64)|Wkv(64)]
__device__ __half g_wq_h   [(size_t)1024 * 64];
__device__ __half g_wkv_h  [(size_t)2048 * 64];
__device__ __half g_wproj_h[(size_t)1024 * 1024];
// attention tensors, per-head layout [(b*16+h)][seq][64]
__device__ __half g_qh[(size_t)NTOK * 1024];
__device__ __half g_ql[(size_t)NTOK * 1024];
__device__ __half g_kh[(size_t)NTOK * 1024];
__device__ __half g_vh[(size_t)NTOK * 1024];

#define QSCALE (0.125f * 1.4426950408889634f)   // fold softmax scale * log2e

// ---------------- helpers ---------------------------------------------------
static __device__ __forceinline__ uint32_t smem_u32(const void* p) {
    uint32_t a;
    asm("{ .reg .u64 t; cvta.to.shared.u64 t, %1; cvt.u32.u64 %0, t; }"
        : "=r"(a) : "l"(p));
    return a;
}
static __device__ __forceinline__ uint32_t hpack(float lo, float hi) {
    uint32_t r;
    asm("cvt.rn.f16x2.f32 %0, %1, %2;" : "=r"(r) : "f"(hi), "f"(lo));
    return r;
}
static __device__ __forceinline__ void split2h(float x, float y,
                                               uint32_t& h, uint32_t& l) {
    h = hpack(x, y);
    __half2 hb = *reinterpret_cast<__half2*>(&h);
    l = hpack(x - __half2float(hb.x), y - __half2float(hb.y));
}
static __device__ __forceinline__ float ex2f(float x) {
    float y; asm("ex2.approx.f32 %0, %1;" : "=f"(y) : "f"(x)); return y;
}
// swizzled smem addr: 128B rows of 8 x 16B chunks, chunk ^= row&7
static __device__ __forceinline__ uint32_t lda(uint32_t base, int row, int ch) {
    return base + row * 128 + (((uint32_t)ch ^ ((uint32_t)row & 7u)) << 4);
}
// paired-row layout for 64B rows: 2 rows per 128B line, conflict-free swizzle
static __device__ __forceinline__ uint32_t ldb(uint32_t base, int row, int ch) {
    return base + (uint32_t)(row >> 1) * 128 +
           (((((uint32_t)row & 1u) << 2 | (uint32_t)ch) ^ (((uint32_t)row >> 1) & 7u)) << 4);
}

#define MMAF(c, a0, a1, a2, a3, b0, b1)                                        \
    asm volatile("mma.sync.aligned.m16n8k16.row.col.f32.f16.f16.f32 "          \
        "{%0,%1,%2,%3},{%4,%5,%6,%7},{%8,%9},{%0,%1,%2,%3};"                   \
        : "+f"((c)[0]), "+f"((c)[1]), "+f"((c)[2]), "+f"((c)[3])               \
        : "r"(a0), "r"(a1), "r"(a2), "r"(a3), "r"(b0), "r"(b1))

// fp16 x2: A = hi+lo (exact), B = plain fp16
#define MMAX2(c, ah, al, b0, b1) do {                                          \
    MMAF(c, (ah)[0], (ah)[1], (ah)[2], (ah)[3], b0, b1);                       \
    MMAF(c, (al)[0], (al)[1], (al)[2], (al)[3], b0, b1);                       \
} while (0)

#define LDSM4(r, addr)                                                         \
    asm volatile("ldmatrix.sync.aligned.m8n8.x4.shared.b16 {%0,%1,%2,%3}, [%4];" \
        : "=r"((r)[0]), "=r"((r)[1]), "=r"((r)[2]), "=r"((r)[3]) : "r"(addr))
#define LDSM4T(r, addr)                                                        \
    asm volatile("ldmatrix.sync.aligned.m8n8.x4.trans.shared.b16 {%0,%1,%2,%3}, [%4];" \
        : "=r"((r)[0]), "=r"((r)[1]), "=r"((r)[2]), "=r"((r)[3]) : "r"(addr))
#define CPA16(dst, src)                                                        \
    asm volatile("cp.async.cg.shared.global [%0], [%1], 16;" :: "r"(dst), "l"(src))
#define CPCOMMIT() asm volatile("cp.async.commit_group;" ::: "memory")
#define CPWAIT(n)  asm volatile("cp.async.wait_group %0;" :: "n"(n) : "memory")

// ======================================================================
// split / convert kernels
// ======================================================================
__global__ __launch_bounds__(256) void xsplit_h(
    const float* __restrict__ X, __half* __restrict__ O,
    int K, int nf4)
{
    int idx = blockIdx.x * 256 + threadIdx.x;
    if (idx >= nf4) return;
    int K4 = K >> 2;
    int n = idx / K4, k4 = idx - n * K4;
    float4 v = *(const float4*)&X[(size_t)n * K + k4 * 4];
    int k = k4 * 4, kc = k >> 5, p = k & 31;
    size_t o = ((size_t)n * (K >> 5) + kc) * 64 + p;
    uint32_t h0, l0, h1, l1;
    split2h(v.x, v.y, h0, l0); split2h(v.z, v.w, h1, l1);
    *(uint32_t*)&O[o]      = h0;  *(uint32_t*)&O[o + 2]  = h1;
    *(uint32_t*)&O[o + 32] = l0;  *(uint32_t*)&O[o + 34] = l1;
}

static __device__ __forceinline__ void copy_h4(
    const float* __restrict__ W, __half* __restrict__ O, int rel)
{
    float4 v = *(const float4*)&W[(size_t)rel * 4];
    *(uint32_t*)&O[(size_t)rel * 4]     = hpack(v.x, v.y);
    *(uint32_t*)&O[(size_t)rel * 4 + 2] = hpack(v.z, v.w);
}

__global__ __launch_bounds__(256) void wconv5(
    const float* __restrict__ wq_b,  const float* __restrict__ wkv_b,
    const float* __restrict__ w_q_a, const float* __restrict__ w_kv_a,
    const float* __restrict__ w_proj,
    __half* __restrict__ owq,   __half* __restrict__ owkv,
    __half* __restrict__ owlat, __half* __restrict__ owproj)
{
    int idx = blockIdx.x * 256 + threadIdx.x;
    if (idx < 16384)        copy_h4(wq_b,   owq,             idx);
    else if (idx < 49152)   copy_h4(wkv_b,  owkv,            idx - 16384);
    else if (idx < 65536)   copy_h4(w_q_a,  owlat,           idx - 49152);
    else if (idx < 81920)   copy_h4(w_kv_a, owlat + 65536,   idx - 65536);
    else if (idx < 344064)  copy_h4(w_proj, owproj,          idx - 81920);
}

// ======================================================================
// gemm_h_body<MODE,KC,NN>: C = A[M,K] @ B[N,K]^T, fp16 x2. (unchanged)
// ======================================================================
#define GEMMH_SMEM 73728

template<int MODE, int KC, int NN>
static __device__ __forceinline__ void gemm_h_body(
    const __half* __restrict__ A, const __half* __restrict__ B,
    float* __restrict__ Cf,
    __half* __restrict__ H, __half* __restrict__ L, __half* __restrict__ H2,
    int m0, int n0, uint32_t base)
{
    const int tid = threadIdx.x;
    const int w = tid >> 5, lane = tid & 31;
    const int g = lane >> 2, tig = lane & 3;
    const int l8 = lane & 7, sub = lane >> 3;
    const int wm = w & 1, wn = w >> 1;

    int rowa[4], cha[4];
    uint32_t soa[4];
    const __half* pa[4];
    #pragma unroll
    for (int p = 0; p < 4; p++) {
        int idx = tid + p * 256;
        rowa[p] = idx >> 3; cha[p] = idx & 7;
        soa[p] = (uint32_t)rowa[p] * 128 +
                 (((uint32_t)cha[p] ^ ((uint32_t)rowa[p] & 7u)) << 4);
        pa[p] = A + (size_t)(m0 + rowa[p]) * KC * 64 + cha[p] * 8;
    }
    int rowb[2], chb[2];
    uint32_t sob[2];
    const __half* pb[2];
    #pragma unroll
    for (int p = 0; p < 2; p++) {
        int idx = tid + p * 256;
        rowb[p] = idx >> 2; chb[p] = idx & 3;
        sob[p] = ldb(0, rowb[p], chb[p]);
        pb[p] = B + (size_t)(n0 + rowb[p]) * KC * 32 + chb[p] * 8;
    }

    float c[4][4][4] = {};

    #pragma unroll
    for (int s = 0; s < 3; s++) {
        if (s < KC) {
            #pragma unroll
            for (int p = 0; p < 4; p++)
                CPA16(base + s * 24576 + soa[p], pa[p] + s * 64);
            #pragma unroll
            for (int p = 0; p < 2; p++)
                CPA16(base + s * 24576 + 16384 + sob[p], pb[p] + s * 32);
        }
        CPCOMMIT();
    }

    #pragma unroll 3
    for (int cc = 0; cc < KC; cc++) {
        const int rb = cc % 3;
        const uint32_t Ab = base + rb * 24576;
        const uint32_t Bb = Ab + 16384;
        CPWAIT(2);
        __syncthreads();

        #pragma unroll
        for (int ks = 0; ks < 2; ks++) {
            uint32_t ah[4][4], al[4][4];
            #pragma unroll
            for (int mt = 0; mt < 4; mt++) {
                int arow = wm * 64 + mt * 16 + l8 + ((sub & 1) << 3);
                int hch  = 2 * ks + (sub >> 1);
                LDSM4(ah[mt], lda(Ab, arow, hch));
                LDSM4(al[mt], lda(Ab, arow, hch + 4));
            }
            #pragma unroll
            for (int np = 0; np < 2; np++) {
                int brow = wn * 32 + np * 16 + ((sub >> 1) << 3) + l8;
                int bch  = 2 * ks + (sub & 1);
                uint32_t bhf[4];
                LDSM4(bhf, ldb(Bb, brow, bch));
                #pragma unroll
                for (int mt = 0; mt < 4; mt++) {
                    MMAX2(c[mt][2*np],   ah[mt], al[mt], bhf[0], bhf[1]);
                    MMAX2(c[mt][2*np+1], ah[mt], al[mt], bhf[2], bhf[3]);
                }
            }
        }

        __syncthreads();
        if (cc + 3 < KC) {
            #pragma unroll
            for (int p = 0; p < 4; p++)
                CPA16(Ab + soa[p], pa[p] + (cc + 3) * 64);
            #pragma unroll
            for (int p = 0; p < 2; p++)
                CPA16(Bb + sob[p], pb[p] + (cc + 3) * 32);
        }
        CPCOMMIT();
    }

    if (MODE == 2) {
        #pragma unroll
        for (int mt = 0; mt < 4; mt++)
            #pragma unroll
            for (int nt = 0; nt < 4; nt++) {
                int r0 = m0 + wm * 64 + mt * 16 + g;
                int col = n0 + wn * 32 + nt * 8 + 2 * tig;
                *(float2*)&Cf[(size_t)r0 * NN + col]       = make_float2(c[mt][nt][0], c[mt][nt][1]);
                *(float2*)&Cf[(size_t)(r0 + 8) * NN + col] = make_float2(c[mt][nt][2], c[mt][nt][3]);
            }
    } else if (MODE == 0) {
        #pragma unroll
        for (int mt = 0; mt < 4; mt++)
            #pragma unroll
            for (int nt = 0; nt < 4; nt++) {
                int tok = m0 + wm * 64 + mt * 16 + g;
                int col = n0 + wn * 32 + nt * 8 + 2 * tig;
                int b = tok >> 11, tn = tok & 2047;
                int h = col >> 6, d = col & 63;
                size_t a0 = (((size_t)b * 16 + h) * SEQ + tn) * 64 + d;
                size_t a1 = a0 + 8 * 64;
                uint32_t hp, lp;
                split2h(c[mt][nt][0] * QSCALE, c[mt][nt][1] * QSCALE, hp, lp);
                *(uint32_t*)&H[a0] = hp;  *(uint32_t*)&L[a0] = lp;
                split2h(c[mt][nt][2] * QSCALE, c[mt][nt][3] * QSCALE, hp, lp);
                *(uint32_t*)&H[a1] = hp;  *(uint32_t*)&L[a1] = lp;
            }
    } else {
        #pragma unroll
        for (int mt = 0; mt < 4; mt++)
            #pragma unroll
            for (int nt = 0; nt < 4; nt++) {
                int tok = m0 + wm * 64 + mt * 16 + g;
                int col = n0 + wn * 32 + nt * 8 + 2 * tig;
                int b = tok >> 11, tn = tok & 2047;
                int h = col >> 7, rr = col & 127, d = rr & 63;
                __half* D = (rr < 64) ? H : H2;   // k or v
                size_t a0 = (((size_t)b * 16 + h) * SEQ + tn) * 64 + d;
                size_t a1 = a0 + 8 * 64;
                *(uint32_t*)&D[a0] = hpack(c[mt][nt][0], c[mt][nt][1]);
                *(uint32_t*)&D[a1] = hpack(c[mt][nt][2], c[mt][nt][3]);
            }
    }
}

__global__ __launch_bounds__(256, 2) void gemm_up_all(
    const __half* __restrict__ qlat,  const __half* __restrict__ wq,
    const __half* __restrict__ kvlat, const __half* __restrict__ wkv,
    __half* __restrict__ qh, __half* __restrict__ ql,
    __half* __restrict__ kh, __half* __restrict__ vh)
{
    extern __shared__ char smraw[];
    const uint32_t base = smem_u32(smraw);
    const int m0 = blockIdx.y * 128;
    if (blockIdx.x < 8)
        gemm_h_body<0, 2, 1024>(qlat, wq, nullptr, qh, ql, nullptr,
                                m0, blockIdx.x * 128, base);
    else
        gemm_h_body<1, 2, 2048>(kvlat, wkv, nullptr, kh, nullptr, vh,
                                m0, (blockIdx.x - 8) * 128, base);
}

__global__ __launch_bounds__(256, 2) void gemm_out_h(
    const __half* __restrict__ A, const __half* __restrict__ B,
    float* __restrict__ Cf)
{
    extern __shared__ char smraw[];
    const uint32_t base = smem_u32(smraw);
    gemm_h_body<2, 32, 1024>(A, B, Cf, nullptr, nullptr, nullptr,
                             blockIdx.y * 128, blockIdx.x * 128, base);
}

// ======================================================================
// gemm_latf3: fused latent projections, fp16 x2. (unchanged)
// ======================================================================
#define LATF_SMEM 49152

__global__ __launch_bounds__(256, 2) void gemm_latf3(
    const __half* __restrict__ A, const __half* __restrict__ B,
    const float* __restrict__ nwq, const float* __restrict__ nwkv,
    __half* __restrict__ Cq, __half* __restrict__ Ckv)
{
    extern __shared__ char smraw[];
    const uint32_t base = smem_u32(smraw);
    __shared__ float nws[128];

    const int tid = threadIdx.x;
    const int w = tid >> 5, lane = tid & 31;
    const int g = lane >> 2, tig = lane & 3;
    const int l8 = lane & 7, sub = lane >> 3;
    const int wm = w >> 1, wn = w & 1;
    const int m0 = blockIdx.x * 64;

    if (tid < 64)       nws[tid] = nwq[tid];
    else if (tid < 128) nws[tid] = nwkv[tid - 64];

    int rowA[2], chA[2], rowB[2], chB[2];
    uint32_t soA[2], soB[2];
    const __half *pA[2], *pB[2];
    #pragma unroll
    for (int p = 0; p < 2; p++) {
        int idx = tid + p * 256;
        rowA[p] = idx >> 3; chA[p] = idx & 7;
        soA[p] = (uint32_t)rowA[p] * 128 +
                 (((uint32_t)chA[p] ^ ((uint32_t)rowA[p] & 7u)) << 4);
        pA[p] = A + (size_t)(m0 + rowA[p]) * 2048 + chA[p] * 8;
        rowB[p] = idx >> 2; chB[p] = idx & 3;
        soB[p] = ldb(0, rowB[p], chB[p]);
        pB[p] = B + (size_t)rowB[p] * 1024 + chB[p] * 8;
    }

    float c[8][4] = {};

    #pragma unroll
    for (int s = 0; s < 3; s++) {
        const uint32_t Ab = base + s * 16384, Bb = Ab + 8192;
        #pragma unroll
        for (int p = 0; p < 2; p++) {
            CPA16(Ab + soA[p], pA[p] + s * 64);
            CPA16(Bb + soB[p], pB[p] + s * 32);
        }
        CPCOMMIT();
    }

    #pragma unroll 3
    for (int cc = 0; cc < 32; cc++) {
        const int rb = cc % 3;
        const uint32_t Ab = base + rb * 16384, Bb = Ab + 8192;
        CPWAIT(2);
        __syncthreads();

        #pragma unroll
        for (int ks = 0; ks < 2; ks++) {
            uint32_t ah[4], al[4];
            {
                int arow = wm * 16 + l8 + ((sub & 1) << 3);
                int hch  = 2 * ks + (sub >> 1);
                LDSM4(ah, lda(Ab, arow, hch));
                LDSM4(al, lda(Ab, arow, hch + 4));
            }
            #pragma unroll
            for (int np = 0; np < 4; np++) {
                int brow = wn * 64 + np * 16 + ((sub >> 1) << 3) + l8;
                int bch  = 2 * ks + (sub & 1);
                uint32_t bhf[4];
                LDSM4(bhf, ldb(Bb, brow, bch));
                MMAX2(c[2*np],   ah, al, bhf[0], bhf[1]);
                MMAX2(c[2*np+1], ah, al, bhf[2], bhf[3]);
            }
        }

        __syncthreads();
        if (cc + 3 < 32) {
            #pragma unroll
            for (int p = 0; p < 2; p++) {
                CPA16(Ab + soA[p], pA[p] + (cc + 3) * 64);
                CPA16(Bb + soB[p], pB[p] + (cc + 3) * 32);
            }
        }
        CPCOMMIT();
    }

    float p0 = 0.f, p1 = 0.f;
    #pragma unroll
    for (int nt = 0; nt < 8; nt++) {
        p0 += c[nt][0]*c[nt][0] + c[nt][1]*c[nt][1];
        p1 += c[nt][2]*c[nt][2] + c[nt][3]*c[nt][3];
    }
    p0 += __shfl_xor_sync(0xffffffffu, p0, 1);
    p0 += __shfl_xor_sync(0xffffffffu, p0, 2);
    p1 += __shfl_xor_sync(0xffffffffu, p1, 1);
    p1 += __shfl_xor_sync(0xffffffffu, p1, 2);
    float s0 = rsqrtf(p0 * (1.0f/64.0f) + 1e-6f);
    float s1 = rsqrtf(p1 * (1.0f/64.0f) + 1e-6f);

    __half* C = wn ? Ckv : Cq;
    const int r = m0 + wm * 16 + g;
    #pragma unroll
    for (int nt = 0; nt < 8; nt++) {
        int col = nt * 8 + 2 * tig;
        float w0 = nws[wn * 64 + col], w1 = nws[wn * 64 + col + 1];
        int kc = col >> 5, p = col & 31;
        uint32_t hh, ll;
        size_t b0 = ((size_t)r * 2 + kc) * 64 + p;
        split2h(c[nt][0]*s0*w0, c[nt][1]*s0*w1, hh, ll);
        *(uint32_t*)&C[b0] = hh;  *(uint32_t*)&C[b0 + 32] = ll;
        size_t b1 = ((size_t)(r + 8) * 2 + kc) * 64 + p;
        split2h(c[nt][2]*s1*w0, c[nt][3]*s1*w1, hh, ll);
        *(uint32_t*)&C[b1] = hh;  *(uint32_t*)&C[b1 + 32] = ll;
    }
}

// ======================================================================
// attn_tc: flash attention, fp16 x2 mma.sync.
// Q fragments HOISTED into registers (loaded once); 3-STAGE KV ring
// (Q 32KB + 3 x 16KB = 80KB smem; 2 CTAs/SM).
// ======================================================================
#define ATTN_SMEM 81920

__global__ __launch_bounds__(256, 2) void attn_tc(
    const __half* __restrict__ qh_g, const __half* __restrict__ ql_g,
    const __half* __restrict__ kh_g, const __half* __restrict__ vh_g,
    __half* __restrict__ ys)
{
    extern __shared__ char smraw[];
    const uint32_t base = smem_u32(smraw);
    const uint32_t Qh = base, Ql = base + 16384;
    const uint32_t kvb = base + 32768;   // stage s: Kh at +s*16384, Vh at +8192

    const int tid = threadIdx.x;
    const int w = tid >> 5, lane = tid & 31;
    const int g = lane >> 2, tig = lane & 3;
    const int l8 = lane & 7, sub = lane >> 3;
    const int r0 = w * 16;
    const int bh = blockIdx.y;
    const int q0 = blockIdx.x * 128;
    const size_t hb = (size_t)bh * SEQ;

    int rowp[2], chp[2];
    uint32_t sop[2];
    size_t offp[2];
    #pragma unroll
    for (int p = 0; p < 2; p++) {
        int idx = tid + p * 256;
        rowp[p] = idx >> 3; chp[p] = idx & 7;
        sop[p] = (uint32_t)rowp[p] * 128 +
                 (((uint32_t)chp[p] ^ ((uint32_t)rowp[p] & 7u)) << 4);
        offp[p] = (size_t)rowp[p] * 64 + chp[p] * 8;
    }
    const __half* pkh = kh_g + hb * 64;
    const __half* pvh = vh_g + hb * 64;

    // group 0: Q + KV sub-chunk 0
    #pragma unroll
    for (int p = 0; p < 4; p++) {
        int idx = tid + p * 256, row = idx >> 3, ch = idx & 7;
        size_t go = (hb + q0 + row) * 64 + ch * 8;
        CPA16(lda(Qh, row, ch), qh_g + go);
        CPA16(lda(Ql, row, ch), ql_g + go);
    }
    #pragma unroll
    for (int p = 0; p < 2; p++) {
        CPA16(kvb + sop[p],        pkh + offp[p]);
        CPA16(kvb + 8192 + sop[p], pvh + offp[p]);
    }
    CPCOMMIT();
    // groups 1,2: KV sub-chunks 1,2
    #pragma unroll
    for (int s = 1; s < 3; s++) {
        const uint32_t Kb = kvb + s * 16384;
        #pragma unroll
        for (int p = 0; p < 2; p++) {
            size_t go = (size_t)s * 4096 + offp[p];
            CPA16(Kb + sop[p],        pkh + go);
            CPA16(Kb + 8192 + sop[p], pvh + go);
        }
        CPCOMMIT();
    }

    // wait for group 0 (Q + KV0), hoist Q fragments into registers
    CPWAIT(2);
    __syncthreads();
    uint32_t qfh[4][4], qfl[4][4];
    {
        const int arow = r0 + l8 + ((sub & 1) << 3);
        #pragma unroll
        for (int ks = 0; ks < 4; ks++) {
            int ach = 2 * ks + (sub >> 1);
            LDSM4(qfh[ks], lda(Qh, arow, ach));
            LDSM4(qfl[ks], lda(Ql, arow, ach));
        }
    }

    float o[8][4] = {};
    float lsum0 = 0.f, lsum1 = 0.f;
    size_t goff = 3 * 4096;

    #pragma unroll 3
    for (int sc = 0; sc < 32; sc++) {
        const int bi = sc % 3;
        const uint32_t Kh = kvb + bi * 16384, Vh = Kh + 8192;
        CPWAIT(2);
        __syncthreads();

        // S = (Qh + Ql) @ Kh^T   (Q fragments already in registers)
        float s[8][4] = {};
        #pragma unroll
        for (int ks = 0; ks < 4; ks++) {
            #pragma unroll
            for (int ntp = 0; ntp < 4; ntp++) {
                int krow = ntp * 16 + ((sub >> 1) << 3) + l8;
                int kch  = 2 * ks + (sub & 1);
                uint32_t bhf[4];
                LDSM4(bhf, lda(Kh, krow, kch));
                MMAX2(s[2 * ntp],     qfh[ks], qfl[ks], bhf[0], bhf[1]);
                MMAX2(s[2 * ntp + 1], qfh[ks], qfl[ks], bhf[2], bhf[3]);
            }
        }

        // p = ex2(s) (fp16 hi+lo); O += (Ph + Pl) @ Vh
        #pragma unroll
        for (int ks = 0; ks < 4; ks++) {
            float e0 = ex2f(s[2*ks][0]),   e1 = ex2f(s[2*ks][1]);
            float e2 = ex2f(s[2*ks][2]),   e3 = ex2f(s[2*ks][3]);
            float e4 = ex2f(s[2*ks+1][0]), e5 = ex2f(s[2*ks+1][1]);
            float e6 = ex2f(s[2*ks+1][2]), e7 = ex2f(s[2*ks+1][3]);
            lsum0 += e0 + e1 + e4 + e5;
            lsum1 += e2 + e3 + e6 + e7;
            uint32_t ph[4], pl[4];
            split2h(e0, e1, ph[0], pl[0]);
            split2h(e2, e3, ph[1], pl[1]);
            split2h(e4, e5, ph[2], pl[2]);
            split2h(e6, e7, ph[3], pl[3]);
            #pragma unroll
            for (int ntp = 0; ntp < 4; ntp++) {
                int vrow = ks * 16 + ((sub & 1) << 3) + l8;
                int vch  = 2 * ntp + (sub >> 1);
                uint32_t vhf[4];
                LDSM4T(vhf, lda(Vh, vrow, vch));
                MMAX2(o[2 * ntp],     ph, pl, vhf[0], vhf[1]);
                MMAX2(o[2 * ntp + 1], ph, pl, vhf[2], vhf[3]);
            }
        }

        __syncthreads();
        if (sc + 3 < 32) {
            #pragma unroll
            for (int p = 0; p < 2; p++) {
                size_t go = goff + offp[p];
                CPA16(Kh + sop[p],        pkh + go);
                CPA16(Kh + 8192 + sop[p], pvh + go);
            }
        }
        CPCOMMIT();
        goff += 4096;
    }

    lsum0 += __shfl_xor_sync(0xffffffffu, lsum0, 1);
    lsum0 += __shfl_xor_sync(0xffffffffu, lsum0, 2);
    lsum1 += __shfl_xor_sync(0xffffffffu, lsum1, 1);
    lsum1 += __shfl_xor_sync(0xffffffffu, lsum1, 2);
    float inv0 = 1.0f / lsum0, inv1 = 1.0f / lsum1;

    const int b = bh >> 4, h = bh & 15;
    const size_t tok0 = (size_t)b * SEQ + q0 + r0 + g;
    #pragma unroll
    for (int nt = 0; nt < 8; nt++) {
        int col = nt * 8 + 2 * tig;
        int kc = 2 * h + (col >> 5), p = col & 31;
        uint32_t hh, ll;
        size_t b0 = (tok0 * 32 + kc) * 64 + p;
        split2h(o[nt][0] * inv0, o[nt][1] * inv0, hh, ll);
        *(uint32_t*)&ys[b0] = hh;  *(uint32_t*)&ys[b0 + 32] = ll;
        size_t b1 = ((tok0 + 8) * 32 + kc) * 64 + p;
        split2h(o[nt][2] * inv1, o[nt][3] * inv1, hh, ll);
        *(uint32_t*)&ys[b1] = hh;  *(uint32_t*)&ys[b1 + 32] = ll;
    }
}

// ---------------------------------------------------------------------------
extern "C" void kernel_launch(void* const* d_in, const int* in_sizes, int n_in,
                              void* d_out, int out_size)
{
    const float* x      = (const float*)d_in[0];
    const float* w_kv_a = (const float*)d_in[1];
    const float* w_kv_b = (const float*)d_in[2];
    const float* w_q_a  = (const float*)d_in[3];
    const float* w_q_b  = (const float*)d_in[4];
    const float* w_proj = (const float*)d_in[5];
    const float* kv_nw  = (const float*)d_in[6];
    const float* q_nw   = (const float*)d_in[7];
    float* out = (float*)d_out;

    __half *xs, *wlat_h, *qlat_h, *kvlat_h, *wq_h, *wkv_h, *wproj_h, *ysh;
    __half *qh, *ql, *kh, *vh;
    cudaGetSymbolAddress((void**)&xs,      g_xs);
    cudaGetSymbolAddress((void**)&wlat_h,  g_wlat_h);
    cudaGetSymbolAddress((void**)&qlat_h,  g_qlat_h);
    cudaGetSymbolAddress((void**)&kvlat_h, g_kvlat_h);
    cudaGetSymbolAddress((void**)&wq_h,    g_wq_h);
    cudaGetSymbolAddress((void**)&wkv_h,   g_wkv_h);
    cudaGetSymbolAddress((void**)&wproj_h, g_wproj_h);
    cudaGetSymbolAddress((void**)&ysh,     g_ysh);
    cudaGetSymbolAddress((void**)&qh, g_qh);  cudaGetSymbolAddress((void**)&ql, g_ql);
    cudaGetSymbolAddress((void**)&kh, g_kh);  cudaGetSymbolAddress((void**)&vh, g_vh);

    cudaFuncSetAttribute(attn_tc,     cudaFuncAttributeMaxDynamicSharedMemorySize, ATTN_SMEM);
    cudaFuncSetAttribute(gemm_up_all, cudaFuncAttributeMaxDynamicSharedMemorySize, GEMMH_SMEM);
    cudaFuncSetAttribute(gemm_out_h,  cudaFuncAttributeMaxDynamicSharedMemorySize, GEMMH_SMEM);
    cudaFuncSetAttribute(gemm_latf3,  cudaFuncAttributeMaxDynamicSharedMemorySize, LATF_SMEM);

    // pre-convert: x -> fp16 split (own launch), weights -> plain fp16 (one launch)
    xsplit_h<<<8192, 256>>>(x, xs, 1024, 2097152);
    wconv5<<<1344, 256>>>(w_q_b, w_kv_b, w_q_a, w_kv_a, w_proj,
                          wq_h, wkv_h, wlat_h, wproj_h);

    // fused latent projections + rmsnorm (fp16 x2) -> fp16 split latents
    gemm_latf3<<<128, 256, LATF_SMEM>>>(xs, wlat_h, q_nw, kv_nw, qlat_h, kvlat_h);

    // merged up-projections (fp16 x2) -> fp16 attention tensors
    gemm_up_all<<<dim3(24, 64), 256, GEMMH_SMEM>>>(qlat_h, wq_h, kvlat_h, wkv_h,
                                                   qh, ql, kh, vh);

    // attention (fp16 x2) -> fp16 hi/lo split y
    attn_tc<<<dim3(16, 64), 256, ATTN_SMEM>>>(qh, ql, kh, vh, ysh);

    // output projection (fp16 x2, fp32 out)
    gemm_out_h<<<dim3(8, 64), 256, GEMMH_SMEM>>>(ysh, wproj_h, out);
}